// round 2
// baseline (speedup 1.0000x reference)
#include <cuda_runtime.h>

#define MARGIN 9.0f
#define NB 32
#define NE 100000
#define ND 64
#define TPB 128
#define EPB 128
#define ROWF 68   // padded entity row stride (floats): conflict-free LDS.128 per 8-lane phase

typedef unsigned long long u64;

__device__ __forceinline__ u64 pack2(float x, float y) {
    u64 r; asm("mov.b64 %0, {%1, %2};" : "=l"(r) : "f"(x), "f"(y)); return r;
}
__device__ __forceinline__ void unpack2(u64 v, float& x, float& y) {
    asm("mov.b64 {%0, %1}, %2;" : "=f"(x), "=f"(y) : "l"(v));
}
// packed 2x fp32 FMA (sm_100+): d = a*b + d  elementwise on f32 pairs
__device__ __forceinline__ void ffma2(u64& d, u64 a, u64 b) {
    asm("fma.rn.f32x2 %0, %1, %2, %0;" : "+l"(d) : "l"(a), "l"(b));
}

__global__ void __launch_bounds__(TPB) transe_kernel(
    const void* __restrict__ subp, const void* __restrict__ relp,
    const float* __restrict__ emb_e, const float* __restrict__ emb_rel,
    float* __restrict__ out)
{
    __shared__ __align__(16) float qt[ND * NB];     // q transposed: [d][b]
    __shared__ float qn[NB];                        // ||q_b||^2
    __shared__ __align__(16) float es[EPB * ROWF];  // entity tile, padded rows

    const int tid = threadIdx.x;

    // ---- index dtype detection (jnp.int64 may have silently become int32) ----
    // Reading 8 int64 = 64 bytes is in-bounds for both layouts (int32 buffer is 128B).
    bool is64 = true;
    {
        const long long* s64 = (const long long*)subp;
        #pragma unroll
        for (int i = 0; i < 8; i++) {
            long long v = s64[i];
            if (v < 0 || v >= NE) is64 = false;
        }
    }

    // ---- build q^T in smem: qt[d*32 + b] = emb_e[sub[b]][d] + emb_rel[rel[b]][d] ----
    for (int i = tid; i < NB * ND; i += TPB) {
        int b = i & (NB - 1);
        int d = i >> 5;
        long long s = is64 ? ((const long long*)subp)[b] : (long long)((const int*)subp)[b];
        long long r = is64 ? ((const long long*)relp)[b] : (long long)((const int*)relp)[b];
        qt[d * NB + b] = emb_e[s * ND + d] + emb_rel[r * ND + d];
    }

    // ---- load 128-entity tile, coalesced float4, into padded smem rows ----
    long long ebase = (long long)blockIdx.x * EPB;
    const float4* src = (const float4*)emb_e;
    for (int i = tid; i < EPB * (ND / 4); i += TPB) {
        int row = i >> 4;     // 16 float4 per row
        int c   = i & 15;
        long long ge = ebase + row;
        float4 v = make_float4(0.f, 0.f, 0.f, 0.f);
        if (ge < NE) v = src[ge * (ND / 4) + c];
        *(float4*)&es[row * ROWF + c * 4] = v;
    }
    __syncthreads();

    // ---- ||q_b||^2: warp 0, lane b; reads qt[d*32 + lane] => consecutive => conflict-free ----
    if (tid < NB) {
        float s = 0.f;
        #pragma unroll
        for (int d = 0; d < ND; d++) { float v = qt[d * NB + tid]; s = fmaf(v, v, s); }
        qn[tid] = s;
    }
    __syncthreads();

    // ---- main accumulation: each thread owns one entity ----
    // acc[p] holds packed (b=2p, b=2p+1); init -qn/2 so dist^2 = en - 2*acc at the end.
    u64 acc[NB / 2];
    #pragma unroll
    for (int p = 0; p < NB / 2; p++)
        acc[p] = pack2(-0.5f * qn[2 * p], -0.5f * qn[2 * p + 1]);

    float en = 0.f;
    const float* myrow = &es[tid * ROWF];

    #pragma unroll 2
    for (int c = 0; c < ND / 4; c++) {
        float4 ev = *(const float4*)&myrow[c * 4];   // LDS.128, phase-conflict-free
        en = fmaf(ev.x, ev.x, en);
        en = fmaf(ev.y, ev.y, en);
        en = fmaf(ev.z, ev.z, en);
        en = fmaf(ev.w, ev.w, en);
        u64 ed[4];
        ed[0] = pack2(ev.x, ev.x);
        ed[1] = pack2(ev.y, ev.y);
        ed[2] = pack2(ev.z, ev.z);
        ed[3] = pack2(ev.w, ev.w);
        #pragma unroll
        for (int k = 0; k < 4; k++) {
            // qt row for dim d = 4c+k: 32 floats = 8 x ulonglong2 (each = 2 packed b-pairs)
            const ulonglong2* qrow = (const ulonglong2*)&qt[(4 * c + k) * NB];
            #pragma unroll
            for (int j = 0; j < 8; j++) {
                ulonglong2 qq = qrow[j];             // LDS.128 broadcast (free, N=1)
                ffma2(acc[2 * j],     ed[k], qq.x);
                ffma2(acc[2 * j + 1], ed[k], qq.y);
            }
        }
    }

    // ---- epilogue: dist^2 = en - 2*acc ; out = MARGIN - sqrt(dist^2) ----
    long long e = ebase + tid;
    if (e < NE) {
        #pragma unroll
        for (int p = 0; p < NB / 2; p++) {
            float a0, a1; unpack2(acc[p], a0, a1);
            float d0 = fmaxf(en - 2.f * a0, 0.f);
            float d1 = fmaxf(en - 2.f * a1, 0.f);
            out[(long long)(2 * p) * NE + e]     = MARGIN - sqrtf(d0);  // coalesced across lanes
            out[(long long)(2 * p + 1) * NE + e] = MARGIN - sqrtf(d1);
        }
    }
}

extern "C" void kernel_launch(void* const* d_in, const int* in_sizes, int n_in,
                              void* d_out, int out_size) {
    (void)in_sizes; (void)n_in; (void)out_size;
    const void* sub      = d_in[0];
    const void* rel      = d_in[1];
    const float* emb_e   = (const float*)d_in[2];
    const float* emb_rel = (const float*)d_in[3];
    float* out = (float*)d_out;

    int grid = (NE + EPB - 1) / EPB;   // 782 blocks
    transe_kernel<<<grid, TPB>>>(sub, rel, emb_e, emb_rel, out);
}